// round 15
// baseline (speedup 1.0000x reference)
#include <cuda_runtime.h>
#include <cstdint>

#define CCH 128
#define OCH 128
#define HH  56
#define WW  56
#define BB  32

#define NTHR 448   // 14 warps: og = tid&31 (4 o each), wg = tid>>5 (0..13, 4 w each)
#define NITEMS (BB * HH)   // 1792 row-items per conv
#define PGRID 148          // one persistent CTA per SM

// scratch: intermediate activations + quantized (transposed) weights
__device__ float g_t[(size_t)BB * CCH * HH * WW];     // ~51.4 MB
__device__ float g_w1[9 * CCH * OCH];                  // [i][c][o]
__device__ float g_w2[9 * CCH * OCH];
__device__ unsigned int g_tickets[2];                  // one per conv launch

// Effective LSQ alpha, matching jax grad_scale forward rounding exactly
__device__ __forceinline__ float lsq_alpha_eff(float a, double g) {
    float s32 = (float)g;
    float om  = (float)(1.0 - g);
    return __fadd_rn(__fmul_rn(a, s32), __fmul_rn(a, om));
}

__device__ __forceinline__ void cp_async16(uint32_t saddr, const void* gaddr) {
    asm volatile("cp.async.cg.shared.global [%0], [%1], 16;" :: "r"(saddr), "l"(gaddr));
}
__device__ __forceinline__ void cp_commit() {
    asm volatile("cp.async.commit_group;");
}
__device__ __forceinline__ void cp_wait0() {
    asm volatile("cp.async.wait_group 0;");
}
__device__ __forceinline__ uint32_t smem_u32(const void* p) {
    uint32_t a;
    asm("{ .reg .u64 t; cvta.to.shared.u64 t, %1; cvt.u32.u64 %0, t; }" : "=r"(a) : "l"(p));
    return a;
}

// wq_t[i][c][o] = round(clip(W[i][o][c]/a_eff, -4, 3)) * a_eff
// Also resets both tickets (runs before the conv kernels every launch/replay).
__global__ void quant_w_kernel(const float* __restrict__ W,
                               const float* __restrict__ a_w,
                               float* __restrict__ wt) {
    int idx = blockIdx.x * blockDim.x + threadIdx.x;
    if (idx < 2) g_tickets[idx] = 0u;
    if (idx >= 9 * CCH * OCH) return;
    int o = idx % OCH;
    int c = (idx / OCH) % CCH;
    int i = idx / (OCH * CCH);
    const double gw = 1.0 / sqrt((double)(OCH * CCH * 3));   // 1/sqrt(49152)
    float a = lsq_alpha_eff(a_w[i], gw);
    float v = __fdiv_rn(W[((size_t)i * OCH + o) * CCH + c], a);
    v = fminf(fmaxf(v, -4.f), 3.f);
    wt[idx] = __fmul_rn(rintf(v), a);
}

// Issue cp.async for weight stage s = r*4 + ch into buffer buf. (3072 float4)
__device__ __forceinline__ void stage_w_async(const float* __restrict__ wqt,
                                              float* buf, int s, int tid) {
    const int r  = s >> 2;
    const int ch = s & 3;
    uint32_t sbase = smem_u32(buf);
    #pragma unroll
    for (int k = 0; k < 7; ++k) {
        int idx = tid + k * NTHR;           // float4 index, 0..3071
        if (idx < 3072) {
            int o4  = idx & 31;             // 32 float4 per row
            int row = idx >> 5;             // dw*32 + cc
            int cc  = row & 31;
            int dw  = row >> 5;
            const float* g = wqt + ((size_t)(dw * 3 + r) * CCH + ch * 32 + cc) * OCH + o4 * 4;
            cp_async16(sbase + (uint32_t)idx * 16u, g);
        }
    }
    cp_commit();
}

// Persistent conv: 148 blocks drain NITEMS row-items via a dynamic ticket.
__global__ __launch_bounds__(NTHR, 1)
void conv_kernel(const float* __restrict__ xin,       // [B][C][H][W]
                 const float* __restrict__ wqt,       // [9][C][O], i = dw*3+dh
                 const float* __restrict__ ap_ptr,    // scalar alpha_p
                 const float* __restrict__ gamma, const float* __restrict__ beta,
                 const float* __restrict__ mean,  const float* __restrict__ var,
                 const float* __restrict__ resid,
                 float* __restrict__ out,
                 unsigned int* __restrict__ ticket,
                 int add_res) {
    extern __shared__ float smem[];
    float* xs  = smem;                        // [3][128][58]  (87168 B)
    float* wsA = smem + 3 * CCH * 58;         // [3][32][128]  (49152 B)
    float* wsB = wsA + 3 * 32 * OCH;          // [3][32][128]  (49152 B)
    __shared__ unsigned int s_item;

    const int tid = threadIdx.x;
    const int og  = tid & 31;
    const int wg  = tid >> 5;            // 0..13
    const int o0  = og * 4;
    const int w0  = wg * 4;

    const double gp = 1.0 / sqrt((double)BB * OCH * HH * WW * 3.0);
    const float ap = lsq_alpha_eff(ap_ptr[0], gp);
    // exact-reciprocal fast path when ap is a power of two (alpha_p = 2.0 here)
    const bool  p2  = ((__float_as_int(ap) & 0x7FFFFF) == 0) && (ap > 0.f);
    const float rap = __frcp_rn(ap);

    for (;;) {
        if (tid == 0) s_item = atomicAdd(ticket, 1u);
        __syncthreads();                   // publish s_item; prev item fully done
        const unsigned item = s_item;
        if (item >= (unsigned)NITEMS) return;
        const int h = (int)item % HH;
        const int b = (int)item / HH;

        // prefetch weight stage 0, then stage x rows (overlapped with the cp.async)
        stage_w_async(wqt, wsA, 0, tid);

        for (int idx = tid; idx < 3 * CCH * 58; idx += NTHR) {
            int wi = idx % 58;
            int rc = idx / 58;
            int c  = rc % CCH;
            int r  = rc / CCH;
            int hs = h + r - 1;
            int w  = wi - 1;
            float v = 0.f;
            if ((unsigned)hs < HH && (unsigned)w < WW)
                v = xin[(((size_t)b * CCH + c) * HH + hs) * WW + w];
            xs[idx] = v;
        }

        float out_acc[4][4];
        #pragma unroll
        for (int oi = 0; oi < 4; ++oi)
            #pragma unroll
            for (int wi = 0; wi < 4; ++wi) out_acc[oi][wi] = 0.f;

        float facc[3][4][4];

        for (int s = 0; s < 12; ++s) {          // s = r*4 + ch
            const int r  = s >> 2;
            const int ch = s & 3;
            float* cur = (s & 1) ? wsB : wsA;
            float* nxt = (s & 1) ? wsA : wsB;

            if (ch == 0) {
                #pragma unroll
                for (int dw = 0; dw < 3; ++dw)
                    #pragma unroll
                    for (int oi = 0; oi < 4; ++oi)
                        #pragma unroll
                        for (int wi = 0; wi < 4; ++wi) facc[dw][oi][wi] = 0.f;
            }

            // wait: this thread's stage-s copies landed (only pending group).
            cp_wait0();
            // sync: stage-s visible block-wide; nxt refillable; xs ready (s=0).
            __syncthreads();
            if (s + 1 < 12) stage_w_async(wqt, nxt, s + 1, tid);

            const float* xbase = xs + (r * CCH + ch * 32) * 58 + w0;
            #pragma unroll 4
            for (int cc = 0; cc < 32; ++cc) {
                const float* xp = xbase + cc * 58;     // even offset -> 8B aligned
                float2 xa = *(const float2*)(xp);
                float2 xb = *(const float2*)(xp + 2);
                float2 xc = *(const float2*)(xp + 4);
                float xv[6] = {xa.x, xa.y, xb.x, xb.y, xc.x, xc.y};
                #pragma unroll
                for (int dw = 0; dw < 3; ++dw) {
                    float4 w4 = *(const float4*)(cur + (dw * 32 + cc) * OCH + o0);
                    float wa0 = w4.x, wa1 = w4.y, wa2 = w4.z, wa3 = w4.w;
                    #pragma unroll
                    for (int wi = 0; wi < 4; ++wi) {
                        float xvv = xv[wi + dw];
                        facc[dw][0][wi] = __fmaf_rn(wa0, xvv, facc[dw][0][wi]);
                        facc[dw][1][wi] = __fmaf_rn(wa1, xvv, facc[dw][1][wi]);
                        facc[dw][2][wi] = __fmaf_rn(wa2, xvv, facc[dw][2][wi]);
                        facc[dw][3][wi] = __fmaf_rn(wa3, xvv, facc[dw][3][wi]);
                    }
                }
            }

            if (ch == 3) {
                // per-shift LSQ psum quantization, then accumulate (exact multiples of ap)
                #pragma unroll
                for (int dw = 0; dw < 3; ++dw)
                    #pragma unroll
                    for (int oi = 0; oi < 4; ++oi)
                        #pragma unroll
                        for (int wi = 0; wi < 4; ++wi) {
                            float v = facc[dw][oi][wi];
                            float q = p2 ? __fmul_rn(v, rap) : __fdiv_rn(v, ap);
                            q = fminf(fmaxf(q, -4.f), 3.f);
                            out_acc[oi][wi] = __fadd_rn(out_acc[oi][wi], __fmul_rn(rintf(q), ap));
                        }
            }
        }

        // epilogue: BN (+residual) + ReLU with jax-matching rounding (NO fma contraction)
        const size_t obase0 = ((size_t)b * OCH) * (HH * WW) + (size_t)h * WW + w0;
        #pragma unroll
        for (int oi = 0; oi < 4; ++oi) {
            int o = o0 + oi;
            float invs = __fdiv_rn(gamma[o], sqrtf(__fadd_rn(var[o], 1e-5f)));
            float sh   = __fadd_rn(beta[o], -__fmul_rn(mean[o], invs));
            size_t base = obase0 + (size_t)o * (HH * WW);
            float vals[4];
            #pragma unroll
            for (int wi = 0; wi < 4; ++wi)
                vals[wi] = __fadd_rn(__fmul_rn(out_acc[oi][wi], invs), sh);
            if (add_res) {
                float4 rr = *(const float4*)(resid + base);
                vals[0] = __fadd_rn(vals[0], rr.x); vals[1] = __fadd_rn(vals[1], rr.y);
                vals[2] = __fadd_rn(vals[2], rr.z); vals[3] = __fadd_rn(vals[3], rr.w);
            }
            float4 sv = make_float4(fmaxf(vals[0], 0.f), fmaxf(vals[1], 0.f),
                                    fmaxf(vals[2], 0.f), fmaxf(vals[3], 0.f));
            *(float4*)(out + base) = sv;
        }
    }
}

extern "C" void kernel_launch(void* const* d_in, const int* in_sizes, int n_in,
                              void* d_out, int out_size) {
    const float* x    = (const float*)d_in[0];
    const float* W1   = (const float*)d_in[1];
    const float* a_w1 = (const float*)d_in[2];
    const float* W2   = (const float*)d_in[3];
    const float* a_w2 = (const float*)d_in[4];
    const float* a_p1 = (const float*)d_in[5];
    const float* a_p2 = (const float*)d_in[6];
    const float* g1   = (const float*)d_in[7];
    const float* b1   = (const float*)d_in[8];
    const float* m1   = (const float*)d_in[9];
    const float* v1   = (const float*)d_in[10];
    const float* g2   = (const float*)d_in[11];
    const float* b2   = (const float*)d_in[12];
    const float* m2   = (const float*)d_in[13];
    const float* v2   = (const float*)d_in[14];
    float* out = (float*)d_out;

    float *t, *w1q, *w2q;
    unsigned int* tk;
    cudaGetSymbolAddress((void**)&t,   g_t);
    cudaGetSymbolAddress((void**)&w1q, g_w1);
    cudaGetSymbolAddress((void**)&w2q, g_w2);
    cudaGetSymbolAddress((void**)&tk,  g_tickets);

    const int smem_bytes = (3 * CCH * 58 + 2 * 3 * 32 * OCH) * (int)sizeof(float); // 185472
    cudaFuncSetAttribute(conv_kernel, cudaFuncAttributeMaxDynamicSharedMemorySize, smem_bytes);

    const int nw = 9 * CCH * OCH;
    quant_w_kernel<<<(nw + 255) / 256, 256>>>(W1, a_w1, w1q);   // also resets tickets
    quant_w_kernel<<<(nw + 255) / 256, 256>>>(W2, a_w2, w2q);

    conv_kernel<<<PGRID, NTHR, smem_bytes>>>(x, w1q, a_p1, g1, b1, m1, v1, nullptr, t, tk + 0, 0);
    conv_kernel<<<PGRID, NTHR, smem_bytes>>>(t, w2q, a_p2, g2, b2, m2, v2, x, out, tk + 1, 1);
}

// round 16
// speedup vs baseline: 1.2003x; 1.2003x over previous
#include <cuda_runtime.h>
#include <cstdint>

#define CCH 128
#define OCH 128
#define HH  56
#define WW  56
#define BB  32

#define NTHR 448   // 14 warps: og = tid&31 (4 o each), wg = tid>>5 (0..13, 4 w each)

// scratch: intermediate activations + quantized (transposed) weights
__device__ float g_t[(size_t)BB * CCH * HH * WW];     // ~51.4 MB
__device__ float g_w1[9 * CCH * OCH];                  // [i][c][o]
__device__ float g_w2[9 * CCH * OCH];

// Effective LSQ alpha, matching jax grad_scale forward rounding exactly
__device__ __forceinline__ float lsq_alpha_eff(float a, double g) {
    float s32 = (float)g;
    float om  = (float)(1.0 - g);
    return __fadd_rn(__fmul_rn(a, s32), __fmul_rn(a, om));
}

__device__ __forceinline__ void cp_async16(uint32_t saddr, const void* gaddr) {
    asm volatile("cp.async.cg.shared.global [%0], [%1], 16;" :: "r"(saddr), "l"(gaddr));
}
__device__ __forceinline__ void cp_commit() {
    asm volatile("cp.async.commit_group;");
}
__device__ __forceinline__ void cp_wait0() {
    asm volatile("cp.async.wait_group 0;");
}
__device__ __forceinline__ uint32_t smem_u32(const void* p) {
    uint32_t a;
    asm("{ .reg .u64 t; cvta.to.shared.u64 t, %1; cvt.u32.u64 %0, t; }" : "=r"(a) : "l"(p));
    return a;
}

// wq_t[i][c][o] = round(clip(W[i][o][c]/a_eff, -4, 3)) * a_eff
__global__ void quant_w_kernel(const float* __restrict__ W,
                               const float* __restrict__ a_w,
                               float* __restrict__ wt) {
    int idx = blockIdx.x * blockDim.x + threadIdx.x;
    if (idx >= 9 * CCH * OCH) return;
    int o = idx % OCH;
    int c = (idx / OCH) % CCH;
    int i = idx / (OCH * CCH);
    const double gw = 1.0 / sqrt((double)(OCH * CCH * 3));   // 1/sqrt(49152)
    float a = lsq_alpha_eff(a_w[i], gw);
    float v = __fdiv_rn(W[((size_t)i * OCH + o) * CCH + c], a);
    v = fminf(fmaxf(v, -4.f), 3.f);
    wt[idx] = __fmul_rn(rintf(v), a);
}

// Issue cp.async for weight stage s = r*4 + ch into buffer buf.
// Copies wqt[(dw*3+r)*CCH + ch*32 + cc][0..127] for dw=0..2, cc=0..31  (3072 float4)
__device__ __forceinline__ void stage_w_async(const float* __restrict__ wqt,
                                              float* buf, int s, int tid) {
    const int r  = s >> 2;
    const int ch = s & 3;
    uint32_t sbase = smem_u32(buf);
    #pragma unroll
    for (int k = 0; k < 7; ++k) {
        int idx = tid + k * NTHR;           // float4 index, 0..3071
        if (idx < 3072) {
            int o4  = idx & 31;             // 32 float4 per row
            int row = idx >> 5;             // dw*32 + cc
            int cc  = row & 31;
            int dw  = row >> 5;
            const float* g = wqt + ((size_t)(dw * 3 + r) * CCH + ch * 32 + cc) * OCH + o4 * 4;
            cp_async16(sbase + (uint32_t)idx * 16u, g);
        }
    }
    cp_commit();
}

// One block = one (b, h) output row: out[b][0..127][h][0..55]
__global__ __launch_bounds__(NTHR, 1)
void conv_kernel(const float* __restrict__ xin,       // [B][C][H][W]
                 const float* __restrict__ wqt,       // [9][C][O], i = dw*3+dh
                 const float* __restrict__ ap_ptr,    // scalar alpha_p
                 const float* __restrict__ gamma, const float* __restrict__ beta,
                 const float* __restrict__ mean,  const float* __restrict__ var,
                 const float* __restrict__ resid,
                 float* __restrict__ out,
                 int add_res) {
    extern __shared__ float smem[];
    float* xs  = smem;                        // [3][128][58]  (87168 B)
    float* wsA = smem + 3 * CCH * 58;         // [3][32][128]  (49152 B)
    float* wsB = wsA + 3 * 32 * OCH;          // [3][32][128]  (49152 B)

    const int h   = blockIdx.x;
    const int b   = blockIdx.y;
    const int tid = threadIdx.x;
    const int og  = tid & 31;
    const int wg  = tid >> 5;            // 0..13
    const int o0  = og * 4;
    const int w0  = wg * 4;

    // prefetch weight stage 0, then stage x rows (overlapped with the cp.async)
    stage_w_async(wqt, wsA, 0, tid);

    for (int idx = tid; idx < 3 * CCH * 58; idx += NTHR) {
        int wi = idx % 58;
        int rc = idx / 58;
        int c  = rc % CCH;
        int r  = rc / CCH;
        int hs = h + r - 1;
        int w  = wi - 1;
        float v = 0.f;
        if ((unsigned)hs < HH && (unsigned)w < WW)
            v = xin[(((size_t)b * CCH + c) * HH + hs) * WW + w];
        xs[idx] = v;
    }

    const double gp = 1.0 / sqrt((double)BB * OCH * HH * WW * 3.0);
    const float ap = lsq_alpha_eff(ap_ptr[0], gp);
    // exact-reciprocal fast path when ap is a power of two (alpha_p = 2.0 here)
    const bool  p2  = ((__float_as_int(ap) & 0x7FFFFF) == 0) && (ap > 0.f);
    const float rap = __frcp_rn(ap);

    float out_acc[4][4];
    #pragma unroll
    for (int oi = 0; oi < 4; ++oi)
        #pragma unroll
        for (int wi = 0; wi < 4; ++wi) out_acc[oi][wi] = 0.f;

    float facc[3][4][4];

    for (int s = 0; s < 12; ++s) {          // s = r*4 + ch
        const int r  = s >> 2;
        const int ch = s & 3;
        float* cur = (s & 1) ? wsB : wsA;
        float* nxt = (s & 1) ? wsA : wsB;

        if (ch == 0) {
            #pragma unroll
            for (int dw = 0; dw < 3; ++dw)
                #pragma unroll
                for (int oi = 0; oi < 4; ++oi)
                    #pragma unroll
                    for (int wi = 0; wi < 4; ++wi) facc[dw][oi][wi] = 0.f;
        }

        // wait: this thread's stage-s copies landed (only pending group).
        cp_wait0();
        // sync: (a) every thread's stage-s copies now globally visible,
        //       (b) every thread finished compute(s-1) -> nxt refillable,
        //       (c) xs staging complete (covers s=0).
        __syncthreads();
        if (s + 1 < 12) stage_w_async(wqt, nxt, s + 1, tid);

        const float* xbase = xs + (r * CCH + ch * 32) * 58 + w0;
        #pragma unroll 4
        for (int cc = 0; cc < 32; ++cc) {
            const float* xp = xbase + cc * 58;     // even offset -> 8B aligned
            float2 xa = *(const float2*)(xp);
            float2 xb = *(const float2*)(xp + 2);
            float2 xc = *(const float2*)(xp + 4);
            float xv[6] = {xa.x, xa.y, xb.x, xb.y, xc.x, xc.y};
            #pragma unroll
            for (int dw = 0; dw < 3; ++dw) {
                float4 w4 = *(const float4*)(cur + (dw * 32 + cc) * OCH + o0);
                float wa0 = w4.x, wa1 = w4.y, wa2 = w4.z, wa3 = w4.w;
                #pragma unroll
                for (int wi = 0; wi < 4; ++wi) {
                    float xvv = xv[wi + dw];
                    facc[dw][0][wi] = __fmaf_rn(wa0, xvv, facc[dw][0][wi]);
                    facc[dw][1][wi] = __fmaf_rn(wa1, xvv, facc[dw][1][wi]);
                    facc[dw][2][wi] = __fmaf_rn(wa2, xvv, facc[dw][2][wi]);
                    facc[dw][3][wi] = __fmaf_rn(wa3, xvv, facc[dw][3][wi]);
                }
            }
        }

        if (ch == 3) {
            // per-shift LSQ psum quantization, then accumulate (exact multiples of ap)
            #pragma unroll
            for (int dw = 0; dw < 3; ++dw)
                #pragma unroll
                for (int oi = 0; oi < 4; ++oi)
                    #pragma unroll
                    for (int wi = 0; wi < 4; ++wi) {
                        float v = facc[dw][oi][wi];
                        float q = p2 ? __fmul_rn(v, rap) : __fdiv_rn(v, ap);
                        q = fminf(fmaxf(q, -4.f), 3.f);
                        out_acc[oi][wi] = __fadd_rn(out_acc[oi][wi], __fmul_rn(rintf(q), ap));
                    }
        }
    }

    // epilogue: BN (+residual) + ReLU with jax-matching rounding (NO fma contraction)
    const size_t obase0 = ((size_t)b * OCH) * (HH * WW) + (size_t)h * WW + w0;
    #pragma unroll
    for (int oi = 0; oi < 4; ++oi) {
        int o = o0 + oi;
        float invs = __fdiv_rn(gamma[o], sqrtf(__fadd_rn(var[o], 1e-5f)));
        float sh   = __fadd_rn(beta[o], -__fmul_rn(mean[o], invs));
        size_t base = obase0 + (size_t)o * (HH * WW);
        float vals[4];
        #pragma unroll
        for (int wi = 0; wi < 4; ++wi)
            vals[wi] = __fadd_rn(__fmul_rn(out_acc[oi][wi], invs), sh);
        if (add_res) {
            float4 rr = *(const float4*)(resid + base);
            vals[0] = __fadd_rn(vals[0], rr.x); vals[1] = __fadd_rn(vals[1], rr.y);
            vals[2] = __fadd_rn(vals[2], rr.z); vals[3] = __fadd_rn(vals[3], rr.w);
        }
        float4 sv = make_float4(fmaxf(vals[0], 0.f), fmaxf(vals[1], 0.f),
                                fmaxf(vals[2], 0.f), fmaxf(vals[3], 0.f));
        *(float4*)(out + base) = sv;
    }
}

extern "C" void kernel_launch(void* const* d_in, const int* in_sizes, int n_in,
                              void* d_out, int out_size) {
    const float* x    = (const float*)d_in[0];
    const float* W1   = (const float*)d_in[1];
    const float* a_w1 = (const float*)d_in[2];
    const float* W2   = (const float*)d_in[3];
    const float* a_w2 = (const float*)d_in[4];
    const float* a_p1 = (const float*)d_in[5];
    const float* a_p2 = (const float*)d_in[6];
    const float* g1   = (const float*)d_in[7];
    const float* b1   = (const float*)d_in[8];
    const float* m1   = (const float*)d_in[9];
    const float* v1   = (const float*)d_in[10];
    const float* g2   = (const float*)d_in[11];
    const float* b2   = (const float*)d_in[12];
    const float* m2   = (const float*)d_in[13];
    const float* v2   = (const float*)d_in[14];
    float* out = (float*)d_out;

    float *t, *w1q, *w2q;
    cudaGetSymbolAddress((void**)&t,   g_t);
    cudaGetSymbolAddress((void**)&w1q, g_w1);
    cudaGetSymbolAddress((void**)&w2q, g_w2);

    const int smem_bytes = (3 * CCH * 58 + 2 * 3 * 32 * OCH) * (int)sizeof(float); // 185472
    cudaFuncSetAttribute(conv_kernel, cudaFuncAttributeMaxDynamicSharedMemorySize, smem_bytes);

    const int nw = 9 * CCH * OCH;
    quant_w_kernel<<<(nw + 255) / 256, 256>>>(W1, a_w1, w1q);
    quant_w_kernel<<<(nw + 255) / 256, 256>>>(W2, a_w2, w2q);

    dim3 grid(HH, BB);
    conv_kernel<<<grid, NTHR, smem_bytes>>>(x, w1q, a_p1, g1, b1, m1, v1, nullptr, t, 0);
    conv_kernel<<<grid, NTHR, smem_bytes>>>(t, w2q, a_p2, g2, b2, m2, v2, x, out, 1);
}

// round 17
// speedup vs baseline: 1.2562x; 1.0466x over previous
#include <cuda_runtime.h>
#include <cstdint>

#define CCH 128
#define OCH 128
#define HH  56
#define WW  56
#define BB  32

#define NTHR 448   // 14 warps: og = tid&31 (4 o each), wg = tid>>5 (0..13, 4 w each)
#define XROW 64    // xs row stride (floats); data at [4..59], zeros at [3],[60]

// scratch: intermediate activations + quantized (transposed) weights
__device__ float g_t[(size_t)BB * CCH * HH * WW];     // ~51.4 MB
__device__ float g_w1[9 * CCH * OCH];                  // [i][c][o]
__device__ float g_w2[9 * CCH * OCH];

// Effective LSQ alpha, matching jax grad_scale forward rounding exactly
__device__ __forceinline__ float lsq_alpha_eff(float a, double g) {
    float s32 = (float)g;
    float om  = (float)(1.0 - g);
    return __fadd_rn(__fmul_rn(a, s32), __fmul_rn(a, om));
}

__device__ __forceinline__ void cp_async16(uint32_t saddr, const void* gaddr) {
    asm volatile("cp.async.cg.shared.global [%0], [%1], 16;" :: "r"(saddr), "l"(gaddr));
}
__device__ __forceinline__ void cp_async16_src(uint32_t saddr, const void* gaddr, int src_bytes) {
    asm volatile("cp.async.cg.shared.global [%0], [%1], 16, %2;"
                 :: "r"(saddr), "l"(gaddr), "r"(src_bytes));
}
__device__ __forceinline__ void cp_commit() {
    asm volatile("cp.async.commit_group;");
}
__device__ __forceinline__ void cp_wait0() {
    asm volatile("cp.async.wait_group 0;");
}
__device__ __forceinline__ uint32_t smem_u32(const void* p) {
    uint32_t a;
    asm("{ .reg .u64 t; cvta.to.shared.u64 t, %1; cvt.u32.u64 %0, t; }" : "=r"(a) : "l"(p));
    return a;
}

// Quantize BOTH weight tensors in one launch.
// wq_t[i][c][o] = round(clip(W[i][o][c]/a_eff, -4, 3)) * a_eff
#define NWELEM (9 * CCH * OCH)
__global__ void quant_w_kernel(const float* __restrict__ W1, const float* __restrict__ a_w1,
                               const float* __restrict__ W2, const float* __restrict__ a_w2,
                               float* __restrict__ wt1, float* __restrict__ wt2) {
    int gidx = blockIdx.x * blockDim.x + threadIdx.x;
    if (gidx >= 2 * NWELEM) return;
    const int sel = gidx >= NWELEM;
    const int idx = sel ? gidx - NWELEM : gidx;
    const float* W  = sel ? W2  : W1;
    const float* aw = sel ? a_w2 : a_w1;
    float* wt       = sel ? wt2 : wt1;
    int o = idx % OCH;
    int c = (idx / OCH) % CCH;
    int i = idx / (OCH * CCH);
    const double gw = 1.0 / sqrt((double)(OCH * CCH * 3));   // 1/sqrt(49152)
    float a = lsq_alpha_eff(aw[i], gw);
    float v = __fdiv_rn(W[((size_t)i * OCH + o) * CCH + c], a);
    v = fminf(fmaxf(v, -4.f), 3.f);
    wt[idx] = __fmul_rn(rintf(v), a);
}

// Issue cp.async for weight stage s = r*4 + ch into buffer buf. (3072 float4)
__device__ __forceinline__ void stage_w_async(const float* __restrict__ wqt,
                                              float* buf, int s, int tid) {
    const int r  = s >> 2;
    const int ch = s & 3;
    uint32_t sbase = smem_u32(buf);
    #pragma unroll
    for (int k = 0; k < 7; ++k) {
        int idx = tid + k * NTHR;           // float4 index, 0..3071
        if (idx < 3072) {
            int o4  = idx & 31;             // 32 float4 per row
            int row = idx >> 5;             // dw*32 + cc
            int cc  = row & 31;
            int dw  = row >> 5;
            const float* g = wqt + ((size_t)(dw * 3 + r) * CCH + ch * 32 + cc) * OCH + o4 * 4;
            cp_async16(sbase + (uint32_t)idx * 16u, g);
        }
    }
    cp_commit();
}

// Issue cp.async for all 3 padded x rows: 384 rows x 14 16B chunks = 5376 ops.
// Row `row = r*128+c` lands at xs[row*XROW + 4 .. +59]; OOB h-rows zero-filled.
__device__ __forceinline__ void stage_x_async(const float* __restrict__ xin,
                                              float* xs, int b, int h, int tid) {
    uint32_t sbase = smem_u32(xs);
    #pragma unroll
    for (int k = 0; k < 12; ++k) {
        int i = tid + k * NTHR;             // 0..5375
        if (i < 3 * CCH * 14) {
            int chunk = i % 14;
            int row   = i / 14;             // r*128 + c
            int c     = row & (CCH - 1);
            int r     = row >> 7;
            int hs    = h + r - 1;
            int ok    = ((unsigned)hs < HH) ? 16 : 0;
            int hc    = (hs < 0) ? 0 : ((hs >= HH) ? HH - 1 : hs);
            const float* g = xin + (((size_t)b * CCH + c) * HH + hc) * WW + chunk * 4;
            cp_async16_src(sbase + (uint32_t)(row * XROW + 4 + chunk * 4) * 4u, g, ok);
        }
    }
    cp_commit();
}

// One block = one (b, h) output row: out[b][0..127][h][0..55]
__global__ __launch_bounds__(NTHR, 1)
void conv_kernel(const float* __restrict__ xin,       // [B][C][H][W]
                 const float* __restrict__ wqt,       // [9][C][O], i = dw*3+dh
                 const float* __restrict__ ap_ptr,    // scalar alpha_p
                 const float* __restrict__ gamma, const float* __restrict__ beta,
                 const float* __restrict__ mean,  const float* __restrict__ var,
                 const float* __restrict__ resid,
                 float* __restrict__ out,
                 int add_res) {
    extern __shared__ float smem[];
    float* xs  = smem;                        // [3*128][64]  (98304 B)
    float* wsA = smem + 3 * CCH * XROW;       // [3][32][128] (49152 B)
    float* wsB = wsA + 3 * 32 * OCH;          // [3][32][128] (49152 B)

    const int h   = blockIdx.x;
    const int b   = blockIdx.y;
    const int tid = threadIdx.x;
    const int og  = tid & 31;
    const int wg  = tid >> 5;            // 0..13
    const int o0  = og * 4;
    const int w0  = wg * 4;

    // async prologue: stage-0 weights + all x rows in flight together
    stage_w_async(wqt, wsA, 0, tid);
    stage_x_async(xin, xs, b, h, tid);

    // border zeros at [3] and [60] of each xs row (2 per thread)
    #pragma unroll
    for (int k = 0; k < 2; ++k) {
        int idx = tid + k * NTHR;
        if (idx < 3 * CCH * 2) {
            int row  = idx >> 1;
            int side = idx & 1;
            xs[row * XROW + (side ? 60 : 3)] = 0.f;
        }
    }

    const double gp = 1.0 / sqrt((double)BB * OCH * HH * WW * 3.0);
    const float ap = lsq_alpha_eff(ap_ptr[0], gp);
    // exact-reciprocal fast path when ap is a power of two (alpha_p = 2.0 here)
    const bool  p2  = ((__float_as_int(ap) & 0x7FFFFF) == 0) && (ap > 0.f);
    const float rap = __frcp_rn(ap);

    float out_acc[4][4];
    #pragma unroll
    for (int oi = 0; oi < 4; ++oi)
        #pragma unroll
        for (int wi = 0; wi < 4; ++wi) out_acc[oi][wi] = 0.f;

    float facc[3][4][4];

    for (int s = 0; s < 12; ++s) {          // s = r*4 + ch
        const int r  = s >> 2;
        const int ch = s & 3;
        float* cur = (s & 1) ? wsB : wsA;
        float* nxt = (s & 1) ? wsA : wsB;

        if (ch == 0) {
            #pragma unroll
            for (int dw = 0; dw < 3; ++dw)
                #pragma unroll
                for (int oi = 0; oi < 4; ++oi)
                    #pragma unroll
                    for (int wi = 0; wi < 4; ++wi) facc[dw][oi][wi] = 0.f;
        }

        // wait: this thread's pending cp.async ops landed (stage-s weights; at s=0 also x).
        cp_wait0();
        // sync: copies visible block-wide; nxt refillable; xs border zeros visible.
        __syncthreads();
        if (s + 1 < 12) stage_w_async(wqt, nxt, s + 1, tid);

        const float* xbase = xs + (r * CCH + ch * 32) * XROW + w0;
        #pragma unroll 4
        for (int cc = 0; cc < 32; ++cc) {
            const float* xp = xbase + cc * XROW + 2;   // idx w0+2 (even -> 8B aligned)
            float2 pa = *(const float2*)(xp);
            float2 pb = *(const float2*)(xp + 2);
            float2 pc = *(const float2*)(xp + 4);
            float2 pd = *(const float2*)(xp + 6);
            // xv8[j] = x at w = w0 - 2 + j   (valid data + border zeros at j=1..6)
            float xv8[8] = {pa.x, pa.y, pb.x, pb.y, pc.x, pc.y, pd.x, pd.y};
            #pragma unroll
            for (int dw = 0; dw < 3; ++dw) {
                float4 w4 = *(const float4*)(cur + (dw * 32 + cc) * OCH + o0);
                float wa0 = w4.x, wa1 = w4.y, wa2 = w4.z, wa3 = w4.w;
                #pragma unroll
                for (int wi = 0; wi < 4; ++wi) {
                    float xvv = xv8[wi + dw + 1];      // w = w0 + wi + dw - 1
                    facc[dw][0][wi] = __fmaf_rn(wa0, xvv, facc[dw][0][wi]);
                    facc[dw][1][wi] = __fmaf_rn(wa1, xvv, facc[dw][1][wi]);
                    facc[dw][2][wi] = __fmaf_rn(wa2, xvv, facc[dw][2][wi]);
                    facc[dw][3][wi] = __fmaf_rn(wa3, xvv, facc[dw][3][wi]);
                }
            }
        }

        if (ch == 3) {
            // per-shift LSQ psum quantization, then accumulate (exact multiples of ap)
            #pragma unroll
            for (int dw = 0; dw < 3; ++dw)
                #pragma unroll
                for (int oi = 0; oi < 4; ++oi)
                    #pragma unroll
                    for (int wi = 0; wi < 4; ++wi) {
                        float v = facc[dw][oi][wi];
                        float q = p2 ? __fmul_rn(v, rap) : __fdiv_rn(v, ap);
                        q = fminf(fmaxf(q, -4.f), 3.f);
                        out_acc[oi][wi] = __fadd_rn(out_acc[oi][wi], __fmul_rn(rintf(q), ap));
                    }
        }
    }

    // epilogue: BN (+residual) + ReLU with jax-matching rounding (NO fma contraction)
    const size_t obase0 = ((size_t)b * OCH) * (HH * WW) + (size_t)h * WW + w0;
    #pragma unroll
    for (int oi = 0; oi < 4; ++oi) {
        int o = o0 + oi;
        float invs = __fdiv_rn(gamma[o], sqrtf(__fadd_rn(var[o], 1e-5f)));
        float sh   = __fadd_rn(beta[o], -__fmul_rn(mean[o], invs));
        size_t base = obase0 + (size_t)o * (HH * WW);
        float vals[4];
        #pragma unroll
        for (int wi = 0; wi < 4; ++wi)
            vals[wi] = __fadd_rn(__fmul_rn(out_acc[oi][wi], invs), sh);
        if (add_res) {
            float4 rr = *(const float4*)(resid + base);
            vals[0] = __fadd_rn(vals[0], rr.x); vals[1] = __fadd_rn(vals[1], rr.y);
            vals[2] = __fadd_rn(vals[2], rr.z); vals[3] = __fadd_rn(vals[3], rr.w);
        }
        float4 sv = make_float4(fmaxf(vals[0], 0.f), fmaxf(vals[1], 0.f),
                                fmaxf(vals[2], 0.f), fmaxf(vals[3], 0.f));
        *(float4*)(out + base) = sv;
    }
}

extern "C" void kernel_launch(void* const* d_in, const int* in_sizes, int n_in,
                              void* d_out, int out_size) {
    const float* x    = (const float*)d_in[0];
    const float* W1   = (const float*)d_in[1];
    const float* a_w1 = (const float*)d_in[2];
    const float* W2   = (const float*)d_in[3];
    const float* a_w2 = (const float*)d_in[4];
    const float* a_p1 = (const float*)d_in[5];
    const float* a_p2 = (const float*)d_in[6];
    const float* g1   = (const float*)d_in[7];
    const float* b1   = (const float*)d_in[8];
    const float* m1   = (const float*)d_in[9];
    const float* v1   = (const float*)d_in[10];
    const float* g2   = (const float*)d_in[11];
    const float* b2   = (const float*)d_in[12];
    const float* m2   = (const float*)d_in[13];
    const float* v2   = (const float*)d_in[14];
    float* out = (float*)d_out;

    float *t, *w1q, *w2q;
    cudaGetSymbolAddress((void**)&t,   g_t);
    cudaGetSymbolAddress((void**)&w1q, g_w1);
    cudaGetSymbolAddress((void**)&w2q, g_w2);

    const int smem_bytes = (3 * CCH * XROW + 2 * 3 * 32 * OCH) * (int)sizeof(float); // 196608
    cudaFuncSetAttribute(conv_kernel, cudaFuncAttributeMaxDynamicSharedMemorySize, smem_bytes);

    quant_w_kernel<<<(2 * NWELEM + 255) / 256, 256>>>(W1, a_w1, W2, a_w2, w1q, w2q);

    dim3 grid(HH, BB);
    conv_kernel<<<grid, NTHR, smem_bytes>>>(x, w1q, a_p1, g1, b1, m1, v1, nullptr, t, 0);
    conv_kernel<<<grid, NTHR, smem_bytes>>>(t, w2q, a_p2, g2, b2, m2, v2, x, out, 1);
}